// round 11
// baseline (speedup 1.0000x reference)
#include <cuda_runtime.h>
#include <cuda_bf16.h>
#include <cstdint>
#include <math.h>

#define BB 4
#define NDET 128
#define NT 2048
#define NY 256
#define NX 256
#define DD 256
#define LL 6
#define NHH 8
#define NTOK 256
#define MTOK 1024
#define HD 32
#define IMG (BB*NY*NX)
#define NPIX (NY*NX)
#define TOT (MTOK*DD)

#define OFF_PATCH 0
#define OFF_QKV   65536
#define OFF_WO    1245184
#define OFF_W1    1638400
#define OFF_W2    3211264
#define OFF_PROJ  4784128
#define WTOT      4849664

#define KC   256
#define STR  264
#define SMEM_MEGA ((32 + 128) * STR * 2)   // 84480 B (also >= 64KB attn use)
#define G 128                               // persistent grid size

// ---------------- scratch ----------------------------------------------------
__device__ float          g_bppart[32 * 4 * NPIX];
__device__ float          g_bp  [IMG];
__device__ float          g_z   [TOT];
__device__ __nv_bfloat16  g_yb  [TOT];
__device__ float          g_qkv [MTOK*3*DD];
__device__ __nv_bfloat16  g_h1b [MTOK*4*DD];
__device__ __nv_bfloat16  g_zb  [TOT];
__device__ float          g_pix [TOT];
__device__ __nv_bfloat16  g_wb  [WTOT];
__device__ float          g_gpart[4 * TOT];
__device__ float          g_pm  [BB*NHH*NTOK*2];
__device__ float          g_pl  [BB*NHH*NTOK*2];
__device__ float          g_pacc[BB*NHH*NTOK*2*HD];

// grid barrier state
__device__ unsigned           g_bar_cnt = 0;
__device__ volatile unsigned  g_bar_gen = 0;

__device__ __forceinline__ void grid_sync() {
    __threadfence();
    __syncthreads();
    if (threadIdx.x == 0) {
        unsigned gen = g_bar_gen;
        if (atomicAdd(&g_bar_cnt, 1u) == G - 1) {
            g_bar_cnt = 0;
            __threadfence();
            g_bar_gen = gen + 1;
        } else {
            while (g_bar_gen == gen) __nanosleep(64);
        }
    }
    __syncthreads();
}

__device__ __forceinline__ uint32_t pack_bf2(float x, float y) {
    __nv_bfloat162 t = __floats2bfloat162_rn(x, y);
    return *(uint32_t*)&t;
}
__device__ __forceinline__ uint32_t smem_u32(const void* p) {
    return (uint32_t)__cvta_generic_to_shared(p);
}
__device__ __forceinline__ void cp16(uint32_t dst, const void* src) {
    asm volatile("cp.async.cg.shared.global [%0], [%1], 16;"
                 :: "r"(dst), "l"(src));
}
#define LDSM_X4(r0, r1, r2, r3, a) \
    asm volatile("ldmatrix.sync.aligned.m8n8.x4.shared.b16 {%0,%1,%2,%3}, [%4];" \
                 : "=r"(r0), "=r"(r1), "=r"(r2), "=r"(r3) : "r"(a))
#define MMA16816(acc, a0, a1, a2, a3, blo, bhi) \
    asm volatile( \
        "mma.sync.aligned.m16n8k16.row.col.f32.bf16.bf16.f32 " \
        "{%0,%1,%2,%3}, {%4,%5,%6,%7}, {%8,%9}, {%0,%1,%2,%3};" \
        : "+f"((acc)[0]), "+f"((acc)[1]), "+f"((acc)[2]), "+f"((acc)[3]) \
        : "r"(a0), "r"(a1), "r"(a2), "r"(a3), "r"(blo), "r"(bhi))

// ---------------- bp stage kernel (separate launch; needs 128KB smem) -------
__global__ void bp_stage4_kernel(const float* __restrict__ sino,
                                 const float* __restrict__ lut) {
    extern __shared__ float s[];
    int g  = blockIdx.y;
    int d0 = g * 4;
    for (int i = threadIdx.x; i < 4 * NT * 4; i += 256) {
        int t = i & (NT - 1), b = (i >> 11) & 3, dd = i >> 13;
        s[dd * (NT * 4) + t * 4 + b] = sino[((size_t)(b * NDET) + d0 + dd) * NT + t];
    }
    __syncthreads();
    float ap[4];
#pragma unroll
    for (int dd = 0; dd < 4; dd++)
        ap[dd] = 0.5f - 0.5f * cosf(6.283185307179586f * (float)(d0 + dd) / 127.0f);

    int pbase = blockIdx.x * 8192;
    for (int p = pbase + threadIdx.x; p < pbase + 8192; p += 256) {
        const float4* lp = (const float4*)(lut + (size_t)p * 256);
        float4 la = lp[g * 2], lb2 = lp[g * 2 + 1];
        float acc0 = 0.f, acc1 = 0.f, acc2 = 0.f, acc3 = 0.f;
        float kfv[4] = {la.x, la.z, lb2.x, lb2.z};
        float alv[4] = {la.y, la.w, lb2.y, lb2.w};
#pragma unroll
        for (int dd = 0; dd < 4; dd++) {
            int kf = (int)kfv[dd];
            if (kf >= 0 && kf < NT - 1) {
                float a = alv[dd];
                const float* sb = &s[dd * (NT * 4) + kf * 4];
                float4 s0 = *(const float4*)sb;
                float4 s1 = *(const float4*)(sb + 4);
                acc0 += ap[dd] * (s0.x + a * (s1.x - s0.x));
                acc1 += ap[dd] * (s0.y + a * (s1.y - s0.y));
                acc2 += ap[dd] * (s0.z + a * (s1.z - s0.z));
                acc3 += ap[dd] * (s0.w + a * (s1.w - s0.w));
            }
        }
        g_bppart[((size_t)g * 4 + 0) * NPIX + p] = acc0;
        g_bppart[((size_t)g * 4 + 1) * NPIX + p] = acc1;
        g_bppart[((size_t)g * 4 + 2) * NPIX + p] = acc2;
        g_bppart[((size_t)g * 4 + 3) * NPIX + p] = acc3;
    }
}

// ---------------- GEMM tile (32x128, K-chunk 256 staged) ---------------------
// asrc: 0 A ptr | 1 patchify(g_bp) | 2 attn-combine. Cpart!=null: raw partial.
// mode: 0 store fp32 | 1 gelu->bf16 | 2 += (ldcg) | 3 +pos store
__device__ __forceinline__ void gemm_tile(
        char* smx,
        const __nv_bfloat16* A, const __nv_bfloat16* W, const float* bias,
        float* Cf, __nv_bfloat16* Cb, const float* pos,
        int K, int Nn, int mode, int asrc,
        int m0, int n0, int kb0, float* Cpart) {
    __nv_bfloat16* As = (__nv_bfloat16*)smx;
    __nv_bfloat16* Ws = As + 32 * STR;
    int tid = threadIdx.x;
    int lane = tid & 31, wid = tid >> 5;
    int wm = wid >> 2, wn = wid & 3;

    __syncthreads();   // guard smem reuse across tile iterations

    if (asrc == 0) {
#pragma unroll
        for (int i = 0; i < 4; i++) {
            int idx = tid + i * 256;
            int r = idx >> 5, sg = (idx & 31) * 8;
            cp16(smem_u32(&As[r * STR + sg]), A + (size_t)(m0 + r) * K + kb0 + sg);
        }
    } else if (asrc == 1) {
#pragma unroll
        for (int i = 0; i < 4; i++) {
            int idx = tid + i * 256;
            int r = idx >> 5, k = (idx & 31) * 8;
            int token = m0 + r;
            int b = token >> 8, hp = (token >> 4) & 15, wp = token & 15;
            int py = k >> 4, px = k & 15;
            const float* bpp = g_bp + b * NPIX + (hp * 16 + py) * NX + wp * 16 + px;
            float4 f0 = __ldcg((const float4*)bpp);
            float4 f1 = __ldcg((const float4*)(bpp + 4));
            uint4 u;
            u.x = pack_bf2(f0.x, f0.y); u.y = pack_bf2(f0.z, f0.w);
            u.z = pack_bf2(f1.x, f1.y); u.w = pack_bf2(f1.z, f1.w);
            *(uint4*)&As[r * STR + k] = u;
        }
    } else {
#pragma unroll
        for (int i = 0; i < 4; i++) {
            int idx = tid + i * 256;
            int r = idx >> 5, k = (idx & 31) * 8;
            int token = m0 + r;
            int q = token & 255, b = token >> 8;
            int h = k >> 5, c0 = k & 31;
            int p0 = ((b * NHH + h) * NTOK + q) * 2;
            float m1 = __ldcg(&g_pm[p0]), m2 = __ldcg(&g_pm[p0 + 1]);
            float M  = fmaxf(m1, m2);
            float e1 = __expf(m1 - M), e2 = __expf(m2 - M);
            float Lv = e1 * __ldcg(&g_pl[p0]) + e2 * __ldcg(&g_pl[p0 + 1]);
            float r1 = e1 / Lv, r2 = e2 / Lv;
            const float4* a1 = (const float4*)&g_pacc[(size_t)p0 * HD + c0];
            const float4* a2 = (const float4*)&g_pacc[(size_t)(p0 + 1) * HD + c0];
            float4 x0 = __ldcg(a1), x1 = __ldcg(a1 + 1);
            float4 y0 = __ldcg(a2), y1 = __ldcg(a2 + 1);
            uint4 u;
            u.x = pack_bf2(r1*x0.x + r2*y0.x, r1*x0.y + r2*y0.y);
            u.y = pack_bf2(r1*x0.z + r2*y0.z, r1*x0.w + r2*y0.w);
            u.z = pack_bf2(r1*x1.x + r2*y1.x, r1*x1.y + r2*y1.y);
            u.w = pack_bf2(r1*x1.z + r2*y1.z, r1*x1.w + r2*y1.w);
            *(uint4*)&As[r * STR + k] = u;
        }
    }
#pragma unroll
    for (int i = 0; i < 16; i++) {
        int idx = tid + i * 256;
        int r = idx >> 5, sg = (idx & 31) * 8;
        cp16(smem_u32(&Ws[r * STR + sg]), W + (size_t)(n0 + r) * K + kb0 + sg);
    }
    asm volatile("cp.async.commit_group;");
    asm volatile("cp.async.wait_group 0;" ::: "memory");
    __syncthreads();

    uint32_t a_addr = smem_u32(
        &As[(wm * 16 + (lane & 7) + ((lane >> 3) & 1) * 8) * STR + (lane >> 4) * 8]);
    uint32_t b_addr0 = smem_u32(
        &Ws[(wn * 32 + (lane >> 4) * 8 + (lane & 7)) * STR + ((lane >> 3) & 1) * 8]);
    uint32_t b_addr1 = b_addr0 + 16 * STR * 2;

    float acc[4][4];
#pragma unroll
    for (int j = 0; j < 4; j++)
#pragma unroll
        for (int q = 0; q < 4; q++) acc[j][q] = 0.f;

#pragma unroll
    for (int kk = 0; kk < 16; kk++) {
        uint32_t a0, a1, a2, a3;
        LDSM_X4(a0, a1, a2, a3, a_addr);
        uint32_t b00, b01, b10, b11, b20, b21, b30, b31;
        LDSM_X4(b00, b01, b10, b11, b_addr0);
        LDSM_X4(b20, b21, b30, b31, b_addr1);
        a_addr += 32; b_addr0 += 32; b_addr1 += 32;
        MMA16816(acc[0], a0, a1, a2, a3, b00, b01);
        MMA16816(acc[1], a0, a1, a2, a3, b10, b11);
        MMA16816(acc[2], a0, a1, a2, a3, b20, b21);
        MMA16816(acc[3], a0, a1, a2, a3, b30, b31);
    }

#pragma unroll
    for (int nf = 0; nf < 4; nf++) {
        int row = m0 + wm * 16 + (lane >> 2);
        int col = n0 + wn * 32 + nf * 8 + (lane & 3) * 2;
#pragma unroll
        for (int half = 0; half < 2; half++) {
            int r = row + half * 8;
            float v0 = acc[nf][half * 2 + 0];
            float v1 = acc[nf][half * 2 + 1];
            if (Cpart) {
                *(float2*)&Cpart[(size_t)r * Nn + col] = make_float2(v0, v1);
                continue;
            }
            v0 += bias[col];
            v1 += bias[col + 1];
            if (mode == 3) {
                const float* pp = &pos[(size_t)(r & 255) * Nn + col];
                v0 += pp[0]; v1 += pp[1];
            }
            if (mode == 1) {
                v0 = 0.5f * v0 * (1.0f + erff(v0 * 0.7071067811865475f));
                v1 = 0.5f * v1 * (1.0f + erff(v1 * 0.7071067811865475f));
                *(uint32_t*)&Cb[(size_t)r * Nn + col] = pack_bf2(v0, v1);
            } else {
                float* cp = &Cf[(size_t)r * Nn + col];
                if (mode == 2) {
                    float2 o = __ldcg((const float2*)cp);
                    v0 += o.x; v1 += o.y;
                }
                *(float2*)cp = make_float2(v0, v1);
            }
        }
    }
}

// ---------------- LN over g_z -> out (1024 rows = G*8 warps) -----------------
__device__ __forceinline__ void ln_phase(const float* gam, const float* bet,
                                         __nv_bfloat16* outp) {
    int row = blockIdx.x * 8 + (threadIdx.x >> 5);
    int lane = threadIdx.x & 31;
    const float4* r4 = (const float4*)(g_z + (size_t)row * DD);
    float4 a = __ldcg(r4 + lane * 2), b = __ldcg(r4 + lane * 2 + 1);
    float s = (a.x + a.y) + (a.z + a.w) + (b.x + b.y) + (b.z + b.w);
#pragma unroll
    for (int o = 16; o; o >>= 1) s += __shfl_xor_sync(0xffffffffu, s, o);
    float mean = s * (1.0f / DD);
    float d0=a.x-mean, d1=a.y-mean, d2=a.z-mean, d3=a.w-mean;
    float d4=b.x-mean, d5=b.y-mean, d6=b.z-mean, d7=b.w-mean;
    float sq = d0*d0+d1*d1+d2*d2+d3*d3+d4*d4+d5*d5+d6*d6+d7*d7;
#pragma unroll
    for (int o = 16; o; o >>= 1) sq += __shfl_xor_sync(0xffffffffu, sq, o);
    float rs = rsqrtf(sq * (1.0f / DD) + 1e-5f);
    float4 g0 = ((const float4*)gam)[lane*2], g1 = ((const float4*)gam)[lane*2+1];
    float4 e0 = ((const float4*)bet)[lane*2], e1 = ((const float4*)bet)[lane*2+1];
    uint4 u;
    u.x = pack_bf2(d0*rs*g0.x + e0.x, d1*rs*g0.y + e0.y);
    u.y = pack_bf2(d2*rs*g0.z + e0.z, d3*rs*g0.w + e0.w);
    u.z = pack_bf2(d4*rs*g1.x + e1.x, d5*rs*g1.y + e1.y);
    u.w = pack_bf2(d6*rs*g1.z + e1.z, d7*rs*g1.w + e1.w);
    *(uint4*)(outp + (size_t)row * DD + lane * 8) = u;
}

// ---------------- w2 combine + residual + LN (or -> zb) ----------------------
__device__ __forceinline__ void combine_ln_phase(const float* bias,
                                                 const float* gam,
                                                 const float* bet, int doLN) {
    int row = blockIdx.x * 8 + (threadIdx.x >> 5);
    int lane = threadIdx.x & 31;
    size_t base = (size_t)row * DD + lane * 8;
    float v[8];
    {
        float4 z0 = __ldcg((const float4*)&g_z[base]);
        float4 z1 = __ldcg((const float4*)&g_z[base + 4]);
        float4 b0 = *(const float4*)&bias[lane * 8];
        float4 b1 = *(const float4*)&bias[lane * 8 + 4];
        v[0] = z0.x + b0.x; v[1] = z0.y + b0.y;
        v[2] = z0.z + b0.z; v[3] = z0.w + b0.w;
        v[4] = z1.x + b1.x; v[5] = z1.y + b1.y;
        v[6] = z1.z + b1.z; v[7] = z1.w + b1.w;
    }
#pragma unroll
    for (int p = 0; p < 4; p++) {
        float4 p0 = __ldcg((const float4*)&g_gpart[(size_t)p * TOT + base]);
        float4 p1 = __ldcg((const float4*)&g_gpart[(size_t)p * TOT + base + 4]);
        v[0] += p0.x; v[1] += p0.y; v[2] += p0.z; v[3] += p0.w;
        v[4] += p1.x; v[5] += p1.y; v[6] += p1.z; v[7] += p1.w;
    }
    *(float4*)&g_z[base]     = make_float4(v[0], v[1], v[2], v[3]);
    *(float4*)&g_z[base + 4] = make_float4(v[4], v[5], v[6], v[7]);
    if (doLN) {
        float s = (v[0]+v[1])+(v[2]+v[3])+(v[4]+v[5])+(v[6]+v[7]);
#pragma unroll
        for (int o = 16; o; o >>= 1) s += __shfl_xor_sync(0xffffffffu, s, o);
        float mean = s * (1.0f / DD);
        float d[8], sq = 0.f;
#pragma unroll
        for (int j = 0; j < 8; j++) { d[j] = v[j] - mean; sq += d[j]*d[j]; }
#pragma unroll
        for (int o = 16; o; o >>= 1) sq += __shfl_xor_sync(0xffffffffu, sq, o);
        float rs = rsqrtf(sq * (1.0f / DD) + 1e-5f);
        float4 g0 = ((const float4*)gam)[lane*2], g1 = ((const float4*)gam)[lane*2+1];
        float4 e0 = ((const float4*)bet)[lane*2], e1 = ((const float4*)bet)[lane*2+1];
        uint4 u;
        u.x = pack_bf2(d[0]*rs*g0.x + e0.x, d[1]*rs*g0.y + e0.y);
        u.y = pack_bf2(d[2]*rs*g0.z + e0.z, d[3]*rs*g0.w + e0.w);
        u.z = pack_bf2(d[4]*rs*g1.x + e1.x, d[5]*rs*g1.y + e1.y);
        u.w = pack_bf2(d[6]*rs*g1.z + e1.z, d[7]*rs*g1.w + e1.w);
        *(uint4*)(g_yb + base) = u;
    } else {
        uint4 u;
        u.x = pack_bf2(v[0], v[1]); u.y = pack_bf2(v[2], v[3]);
        u.z = pack_bf2(v[4], v[5]); u.w = pack_bf2(v[6], v[7]);
        *(uint4*)(g_zb + base) = u;
    }
}

// ---------------- attention phase: 64 blocks, both kv-halves per block -------
__device__ __forceinline__ void attn_phase(char* smx) {
    if (blockIdx.x >= 64) return;
    float* ks = (float*)smx;                 // [2][128*HD] = 32KB
    float* vs = ks + 2 * 128 * HD;           // 32KB
    int bi = blockIdx.x;
    int qh = bi & 1, h = (bi >> 1) & 7, b = bi >> 4;
    for (int i = threadIdx.x; i < 2 * 128 * HD; i += 256) {
        int kvh = i >> 12, j = i & 4095;
        int m = j >> 5, c = j & 31;
        const float* base = g_qkv + ((size_t)(b * NTOK + kvh * 128 + m)) * (3 * DD) + h * HD + c;
        ks[i] = __ldcg(base + DD);
        vs[i] = __ldcg(base + 2 * DD);
    }
    __syncthreads();
    int kvh = threadIdx.x >> 7;
    int q = qh * 128 + (threadIdx.x & 127);
    const float* qr = g_qkv + (size_t)(b * NTOK + q) * (3 * DD) + h * HD;
    float qv[HD];
#pragma unroll
    for (int c = 0; c < HD; c++) qv[c] = __ldcg(qr + c) * 0.17677669529663687f;
    const float* kb = ks + kvh * 4096;
    const float* vb = vs + kvh * 4096;
    float mmax = -1e30f, l = 0.f, acc[HD];
#pragma unroll
    for (int c = 0; c < HD; c++) acc[c] = 0.f;
    for (int m = 0; m < 128; m++) {
        const float4* kp = (const float4*)&kb[m * HD];
        float s0 = 0.f, s1 = 0.f, s2 = 0.f, s3 = 0.f;
#pragma unroll
        for (int j = 0; j < 8; j++) {
            float4 k4 = kp[j];
            s0 += qv[j*4+0] * k4.x; s1 += qv[j*4+1] * k4.y;
            s2 += qv[j*4+2] * k4.z; s3 += qv[j*4+3] * k4.w;
        }
        float sc = (s0 + s1) + (s2 + s3);
        float nm   = fmaxf(mmax, sc);
        float corr = __expf(mmax - nm);
        float p    = __expf(sc - nm);
        l = l * corr + p;
        const float4* vp = (const float4*)&vb[m * HD];
#pragma unroll
        for (int j = 0; j < 8; j++) {
            float4 v4 = vp[j];
            acc[j*4+0] = acc[j*4+0] * corr + p * v4.x;
            acc[j*4+1] = acc[j*4+1] * corr + p * v4.y;
            acc[j*4+2] = acc[j*4+2] * corr + p * v4.z;
            acc[j*4+3] = acc[j*4+3] * corr + p * v4.w;
        }
        mmax = nm;
    }
    int pidx = ((b * NHH + h) * NTOK + q) * 2 + kvh;
    g_pm[pidx] = mmax;
    g_pl[pidx] = l;
    float4* pa = (float4*)&g_pacc[(size_t)pidx * HD];
#pragma unroll
    for (int j = 0; j < 8; j++)
        pa[j] = make_float4(acc[j*4+0], acc[j*4+1], acc[j*4+2], acc[j*4+3]);
}

// ---------------- the megakernel ---------------------------------------------
__global__ void __launch_bounds__(256)
mega_kernel(const float* __restrict__ pw,  const float* __restrict__ wqkv,
            const float* __restrict__ wo,  const float* __restrict__ w1,
            const float* __restrict__ w2,  const float* __restrict__ prj,
            const float* __restrict__ patch_b, const float* __restrict__ pos,
            const float* __restrict__ ln1_g,   const float* __restrict__ ln1_b,
            const float* __restrict__ bqkv,    const float* __restrict__ bo,
            const float* __restrict__ ln2_g,   const float* __restrict__ ln2_b,
            const float* __restrict__ b1,      const float* __restrict__ b2,
            const float* __restrict__ proj_b,
            const float* __restrict__ conv_w,  const float* __restrict__ conv_b,
            float* __restrict__ out, float* __restrict__ out_bp) {
    extern __shared__ char smx[];
    int tid = threadIdx.x;

    // phase 0: weight conversion + bp reduce
    for (int i = blockIdx.x * 256 + tid; i < WTOT; i += G * 256) {
        float v;
        if      (i < OFF_QKV)  v = pw [i];
        else if (i < OFF_WO)   v = wqkv[i - OFF_QKV];
        else if (i < OFF_W1)   v = wo [i - OFF_WO];
        else if (i < OFF_W2)   v = w1 [i - OFF_W1];
        else if (i < OFF_PROJ) v = w2 [i - OFF_W2];
        else                   v = prj[i - OFF_PROJ];
        g_wb[i] = __float2bfloat16_rn(v);
    }
    for (int idx = blockIdx.x * 256 + tid; idx < IMG; idx += G * 256) {
        int b = idx >> 16, p = idx & (NPIX - 1);
        float sum = 0.f;
#pragma unroll 8
        for (int gg = 0; gg < 32; gg++)
            sum += g_bppart[((size_t)gg * 4 + b) * NPIX + p];
        float v = sum * (1.0f / 63.5f);
        g_bp[idx] = v;
        if (out_bp) out_bp[idx] = v;
    }
    grid_sync();

    // phase 1: patch embed (+pos) [64 tiles]
    for (int t = blockIdx.x; t < 64; t += G)
        gemm_tile(smx, nullptr, g_wb + OFF_PATCH, patch_b, g_z, nullptr, pos,
                  DD, DD, 3, 1, (t >> 1) * 32, (t & 1) * 128, 0, nullptr);
    grid_sync();
    ln_phase(ln1_g, ln1_b, g_yb);
    grid_sync();

    for (int l = 0; l < LL; l++) {
        // qkv [192 tiles]
        const __nv_bfloat16* Wq = g_wb + OFF_QKV + (size_t)l * 3 * DD * DD;
        const float* bq = bqkv + (size_t)l * 3 * DD;
        for (int t = blockIdx.x; t < 192; t += G)
            gemm_tile(smx, g_yb, Wq, bq, g_qkv, nullptr, nullptr,
                      DD, 3 * DD, 0, 0, (t / 6) * 32, (t % 6) * 128, 0, nullptr);
        grid_sync();
        attn_phase(smx);
        grid_sync();
        // WO (attn combine in A-load, += residual) [64 tiles]
        const __nv_bfloat16* Wo = g_wb + OFF_WO + (size_t)l * DD * DD;
        const float* bob = bo + (size_t)l * DD;
        for (int t = blockIdx.x; t < 64; t += G)
            gemm_tile(smx, nullptr, Wo, bob, g_z, nullptr, nullptr,
                      DD, DD, 2, 2, (t >> 1) * 32, (t & 1) * 128, 0, nullptr);
        grid_sync();
        ln_phase(ln2_g + (size_t)l * DD, ln2_b + (size_t)l * DD, g_yb);
        grid_sync();
        // W1 + gelu [256 tiles]
        const __nv_bfloat16* W1p = g_wb + OFF_W1 + (size_t)l * 4 * DD * DD;
        const float* b1p = b1 + (size_t)l * 4 * DD;
        for (int t = blockIdx.x; t < 256; t += G)
            gemm_tile(smx, g_yb, W1p, b1p, nullptr, g_h1b, nullptr,
                      DD, 4 * DD, 1, 0, (t >> 3) * 32, (t & 7) * 128, 0, nullptr);
        grid_sync();
        // W2 split-K(4) [256 tiles]
        const __nv_bfloat16* W2p = g_wb + OFF_W2 + (size_t)l * DD * 4 * DD;
        for (int t = blockIdx.x; t < 256; t += G) {
            int kz = t >> 6, rem = t & 63;
            gemm_tile(smx, g_h1b, W2p, nullptr, nullptr, nullptr, nullptr,
                      4 * DD, DD, 0, 0, (rem >> 1) * 32, (rem & 1) * 128,
                      kz * KC, g_gpart + (size_t)kz * TOT);
        }
        grid_sync();
        if (l < LL - 1)
            combine_ln_phase(b2 + (size_t)l * DD,
                             ln1_g + (size_t)(l + 1) * DD,
                             ln1_b + (size_t)(l + 1) * DD, 1);
        else
            combine_ln_phase(b2 + (size_t)l * DD, nullptr, nullptr, 0);
        grid_sync();
    }

    // proj [64 tiles]
    for (int t = blockIdx.x; t < 64; t += G)
        gemm_tile(smx, g_zb, g_wb + OFF_PROJ, proj_b, g_pix, nullptr, nullptr,
                  DD, DD, 0, 0, (t >> 1) * 32, (t & 1) * 128, 0, nullptr);
    grid_sync();

    // conv (+fused unpatchify) + bias + bp residual
    float cw[9];
#pragma unroll
    for (int j = 0; j < 9; j++) cw[j] = conv_w[j];
    float cbv = conv_b[0];
    for (int idx = blockIdx.x * 256 + tid; idx < IMG; idx += G * 256) {
        int x = idx & 255, y = (idx >> 8) & 255, b = idx >> 16;
        float s = 0.f;
#pragma unroll
        for (int ky = 0; ky < 3; ky++) {
            int yy = y + ky - 1;
            if (yy < 0 || yy >= NY) continue;
#pragma unroll
            for (int kx = 0; kx < 3; kx++) {
                int xx = x + kx - 1;
                if (xx < 0 || xx >= NX) continue;
                float v = __ldcg(&g_pix[(size_t)((b << 8) + (yy >> 4) * 16 + (xx >> 4)) * DD
                                        + (yy & 15) * 16 + (xx & 15)]);
                s += v * cw[ky * 3 + kx];
            }
        }
        out[idx] = s + cbv + __ldcg(&g_bp[idx]);
    }
}

// ---------------- host orchestration ----------------------------------------
extern "C" void kernel_launch(void* const* d_in, const int* in_sizes, int n_in,
                              void* d_out, int out_size) {
    const float* sino    = (const float*)d_in[0];
    const float* lut     = (const float*)d_in[1];
    const float* patch_w = (const float*)d_in[2];
    const float* patch_b = (const float*)d_in[3];
    const float* pos     = (const float*)d_in[4];
    const float* ln1_g   = (const float*)d_in[5];
    const float* ln1_b   = (const float*)d_in[6];
    const float* wqkv    = (const float*)d_in[7];
    const float* bqkv    = (const float*)d_in[8];
    const float* wo      = (const float*)d_in[9];
    const float* bo      = (const float*)d_in[10];
    const float* ln2_g   = (const float*)d_in[11];
    const float* ln2_b   = (const float*)d_in[12];
    const float* w1      = (const float*)d_in[13];
    const float* b1      = (const float*)d_in[14];
    const float* w2      = (const float*)d_in[15];
    const float* b2      = (const float*)d_in[16];
    const float* proj_w  = (const float*)d_in[17];
    const float* proj_b  = (const float*)d_in[18];
    const float* conv_w  = (const float*)d_in[19];
    const float* conv_b  = (const float*)d_in[20];

    float* out = (float*)d_out;
    float* out_bp = (out_size >= 2 * IMG) ? (out + IMG) : nullptr;

    cudaFuncSetAttribute(bp_stage4_kernel, cudaFuncAttributeMaxDynamicSharedMemorySize, 131072);
    cudaFuncSetAttribute(mega_kernel, cudaFuncAttributeMaxDynamicSharedMemorySize, SMEM_MEGA);

    bp_stage4_kernel<<<dim3(8, 32), 256, 131072>>>(sino, lut);
    mega_kernel<<<G, 256, SMEM_MEGA>>>(
        patch_w, wqkv, wo, w1, w2, proj_w,
        patch_b, pos, ln1_g, ln1_b, bqkv, bo, ln2_g, ln2_b,
        b1, b2, proj_b, conv_w, conv_b, out, out_bp);
}

// round 12
// speedup vs baseline: 1.4235x; 1.4235x over previous
#include <cuda_runtime.h>
#include <cuda_bf16.h>
#include <cstdint>
#include <math.h>

#define BB 4
#define NDET 128
#define NT 2048
#define NY 256
#define NX 256
#define DD 256
#define LL 6
#define NHH 8
#define NTOK 256
#define MTOK 1024
#define HD 32
#define IMG (BB*NY*NX)
#define NPIX (NY*NX)
#define TOT (MTOK*DD)

#define OFF_PATCH 0
#define OFF_QKV   65536
#define OFF_WO    1245184
#define OFF_W1    1638400
#define OFF_W2    3211264
#define OFF_PROJ  4784128
#define WTOT      4849664

#define KC   256
#define STR  264
#define SMEM_GM ((32 + 64) * STR * 2)    // 50688 bytes

__device__ float          g_bppart[32 * 4 * NPIX];
__device__ float          g_bp  [IMG];
__device__ float          g_z   [TOT];
__device__ __nv_bfloat16  g_yb  [TOT];
__device__ float          g_qkv [MTOK*3*DD];
__device__ __nv_bfloat16  g_h1b [MTOK*4*DD];
__device__ __nv_bfloat16  g_zb  [TOT];
__device__ float          g_pix [TOT];
__device__ __nv_bfloat16  g_wb  [WTOT];
__device__ float          g_gpart[4 * TOT];
__device__ float          g_pm  [BB*NHH*NTOK*2];
__device__ float          g_pl  [BB*NHH*NTOK*2];
__device__ float          g_pacc[BB*NHH*NTOK*2*HD];

__device__ __forceinline__ uint32_t pack_bf2(float x, float y) {
    __nv_bfloat162 t = __floats2bfloat162_rn(x, y);
    return *(uint32_t*)&t;
}
__device__ __forceinline__ uint32_t smem_u32(const void* p) {
    return (uint32_t)__cvta_generic_to_shared(p);
}
__device__ __forceinline__ void cp16(uint32_t dst, const void* src) {
    asm volatile("cp.async.cg.shared.global [%0], [%1], 16;"
                 :: "r"(dst), "l"(src));
}
#define LDSM_X4(r0, r1, r2, r3, a) \
    asm volatile("ldmatrix.sync.aligned.m8n8.x4.shared.b16 {%0,%1,%2,%3}, [%4];" \
                 : "=r"(r0), "=r"(r1), "=r"(r2), "=r"(r3) : "r"(a))
#define MMA16816(acc, a0, a1, a2, a3, blo, bhi) \
    asm volatile( \
        "mma.sync.aligned.m16n8k16.row.col.f32.bf16.bf16.f32 " \
        "{%0,%1,%2,%3}, {%4,%5,%6,%7}, {%8,%9}, {%0,%1,%2,%3};" \
        : "+f"((acc)[0]), "+f"((acc)[1]), "+f"((acc)[2]), "+f"((acc)[3]) \
        : "r"(a0), "r"(a1), "r"(a2), "r"(a3), "r"(blo), "r"(bhi))

__global__ void wconv_kernel(const float* __restrict__ pw,
                             const float* __restrict__ qkv,
                             const float* __restrict__ wo,
                             const float* __restrict__ w1,
                             const float* __restrict__ w2,
                             const float* __restrict__ prj) {
    int i = blockIdx.x * 256 + threadIdx.x;
    float v;
    if      (i < OFF_QKV)  v = pw [i];
    else if (i < OFF_WO)   v = qkv[i - OFF_QKV];
    else if (i < OFF_W1)   v = wo [i - OFF_WO];
    else if (i < OFF_W2)   v = w1 [i - OFF_W1];
    else if (i < OFF_PROJ) v = w2 [i - OFF_W2];
    else if (i < WTOT)     v = prj[i - OFF_PROJ];
    else return;
    g_wb[i] = __float2bfloat16_rn(v);
}

__global__ void bp_stage4_kernel(const float* __restrict__ sino,
                                 const float* __restrict__ lut) {
    extern __shared__ float s[];
    int g  = blockIdx.y;
    int d0 = g * 4;
    for (int i = threadIdx.x; i < 4 * NT * 4; i += 256) {
        int t = i & (NT - 1), b = (i >> 11) & 3, dd = i >> 13;
        s[dd * (NT * 4) + t * 4 + b] = sino[((size_t)(b * NDET) + d0 + dd) * NT + t];
    }
    __syncthreads();
    float ap[4];
#pragma unroll
    for (int dd = 0; dd < 4; dd++)
        ap[dd] = 0.5f - 0.5f * cosf(6.283185307179586f * (float)(d0 + dd) / 127.0f);

    int pbase = blockIdx.x * 8192;
    for (int p = pbase + threadIdx.x; p < pbase + 8192; p += 256) {
        const float4* lp = (const float4*)(lut + (size_t)p * 256);
        float4 la = lp[g * 2], lb2 = lp[g * 2 + 1];
        float acc0 = 0.f, acc1 = 0.f, acc2 = 0.f, acc3 = 0.f;
        float kfv[4] = {la.x, la.z, lb2.x, lb2.z};
        float alv[4] = {la.y, la.w, lb2.y, lb2.w};
#pragma unroll
        for (int dd = 0; dd < 4; dd++) {
            int kf = (int)kfv[dd];
            if (kf >= 0 && kf < NT - 1) {
                float a = alv[dd];
                const float* sb = &s[dd * (NT * 4) + kf * 4];
                float4 s0 = *(const float4*)sb;
                float4 s1 = *(const float4*)(sb + 4);
                acc0 += ap[dd] * (s0.x + a * (s1.x - s0.x));
                acc1 += ap[dd] * (s0.y + a * (s1.y - s0.y));
                acc2 += ap[dd] * (s0.z + a * (s1.z - s0.z));
                acc3 += ap[dd] * (s0.w + a * (s1.w - s0.w));
            }
        }
        g_bppart[((size_t)g * 4 + 0) * NPIX + p] = acc0;
        g_bppart[((size_t)g * 4 + 1) * NPIX + p] = acc1;
        g_bppart[((size_t)g * 4 + 2) * NPIX + p] = acc2;
        g_bppart[((size_t)g * 4 + 3) * NPIX + p] = acc3;
    }
}

__global__ void bp_reduce_kernel(float* __restrict__ out_bp) {
    int idx = blockIdx.x * blockDim.x + threadIdx.x;
    if (idx >= IMG) return;
    int b = idx >> 16, p = idx & (NPIX - 1);
    float sum = 0.f;
#pragma unroll 8
    for (int gg = 0; gg < 32; gg++)
        sum += g_bppart[((size_t)gg * 4 + b) * NPIX + p];
    float v = sum * (1.0f / 63.5f);
    g_bp[idx] = v;
    if (out_bp) out_bp[idx] = v;
}

// ---- bf16 mma GEMM, tile 32x64, K=256 staged. 8 warps (2m x 4n), warp 16x16.
// asrc: 0 A ptr | 1 patchify(g_bp) | 2 attn combine
// modes: 0 fp32 store | 1 gelu->bf16 | 2 fp32 += | 3 fp32 +bias+pos
// gridDim.z>1: raw partials into Cf[z*1024*Nn]
__global__ void __launch_bounds__(256)
gemm_mma(const __nv_bfloat16* __restrict__ A,
         const __nv_bfloat16* __restrict__ W,
         const float* __restrict__ bias,
         float* __restrict__ Cf,
         __nv_bfloat16* __restrict__ Cb,
         const float* __restrict__ pos,
         int K, int Nn, int mode, int asrc) {
    extern __shared__ __nv_bfloat16 sh[];
    __nv_bfloat16* As = sh;               // 32 x STR
    __nv_bfloat16* Ws = sh + 32 * STR;    // 64 x STR
    int tid = threadIdx.x;
    int lane = tid & 31, wid = tid >> 5;
    int wm = wid >> 2, wn = wid & 3;
    int m0 = blockIdx.y * 32, n0 = blockIdx.x * 64;
    int kb0 = blockIdx.z * KC;

    // ---- stage A (32x256): 1024 segs, 4/thread ----
    if (asrc == 0) {
#pragma unroll
        for (int i = 0; i < 4; i++) {
            int idx = tid + i * 256;
            int r = idx >> 5, sg = (idx & 31) * 8;
            cp16(smem_u32(&As[r * STR + sg]), A + (size_t)(m0 + r) * K + kb0 + sg);
        }
    } else if (asrc == 1) {
#pragma unroll
        for (int i = 0; i < 4; i++) {
            int idx = tid + i * 256;
            int r = idx >> 5, k = (idx & 31) * 8;
            int token = m0 + r;
            int b = token >> 8, hp = (token >> 4) & 15, wp = token & 15;
            int py = k >> 4, px = k & 15;
            const float* bpp = g_bp + b * NPIX + (hp * 16 + py) * NX + wp * 16 + px;
            float4 f0 = *(const float4*)bpp;
            float4 f1 = *(const float4*)(bpp + 4);
            uint4 u;
            u.x = pack_bf2(f0.x, f0.y); u.y = pack_bf2(f0.z, f0.w);
            u.z = pack_bf2(f1.x, f1.y); u.w = pack_bf2(f1.z, f1.w);
            *(uint4*)&As[r * STR + k] = u;
        }
    } else {
#pragma unroll
        for (int i = 0; i < 4; i++) {
            int idx = tid + i * 256;
            int r = idx >> 5, k = (idx & 31) * 8;
            int token = m0 + r;
            int q = token & 255, b = token >> 8;
            int h = k >> 5, c0 = k & 31;
            int p0 = ((b * NHH + h) * NTOK + q) * 2;
            float m1 = g_pm[p0], m2 = g_pm[p0 + 1];
            float M  = fmaxf(m1, m2);
            float e1 = __expf(m1 - M), e2 = __expf(m2 - M);
            float Lv = e1 * g_pl[p0] + e2 * g_pl[p0 + 1];
            float r1 = e1 / Lv, r2 = e2 / Lv;
            const float4* a1 = (const float4*)&g_pacc[(size_t)p0 * HD + c0];
            const float4* a2 = (const float4*)&g_pacc[(size_t)(p0 + 1) * HD + c0];
            float4 x0 = a1[0], x1 = a1[1], y0 = a2[0], y1 = a2[1];
            uint4 u;
            u.x = pack_bf2(r1*x0.x + r2*y0.x, r1*x0.y + r2*y0.y);
            u.y = pack_bf2(r1*x0.z + r2*y0.z, r1*x0.w + r2*y0.w);
            u.z = pack_bf2(r1*x1.x + r2*y1.x, r1*x1.y + r2*y1.y);
            u.w = pack_bf2(r1*x1.z + r2*y1.z, r1*x1.w + r2*y1.w);
            *(uint4*)&As[r * STR + k] = u;
        }
    }
    // ---- stage W (64x256): 2048 segs, 8/thread ----
#pragma unroll
    for (int i = 0; i < 8; i++) {
        int idx = tid + i * 256;
        int r = idx >> 5, sg = (idx & 31) * 8;
        cp16(smem_u32(&Ws[r * STR + sg]), W + (size_t)(n0 + r) * K + kb0 + sg);
    }
    asm volatile("cp.async.commit_group;");
    asm volatile("cp.async.wait_group 0;" ::: "memory");
    __syncthreads();

    uint32_t a_addr = smem_u32(
        &As[(wm * 16 + (lane & 7) + ((lane >> 3) & 1) * 8) * STR + (lane >> 4) * 8]);
    uint32_t b_addr = smem_u32(
        &Ws[(wn * 16 + (lane >> 4) * 8 + (lane & 7)) * STR + ((lane >> 3) & 1) * 8]);

    float acc[2][4];
#pragma unroll
    for (int j = 0; j < 2; j++)
#pragma unroll
        for (int q = 0; q < 4; q++) acc[j][q] = 0.f;

#pragma unroll
    for (int kk = 0; kk < 16; kk++) {
        uint32_t a0, a1, a2, a3;
        LDSM_X4(a0, a1, a2, a3, a_addr);
        uint32_t b00, b01, b10, b11;   // n0: klo,khi ; n1: klo,khi
        LDSM_X4(b00, b01, b10, b11, b_addr);
        a_addr += 32; b_addr += 32;
        MMA16816(acc[0], a0, a1, a2, a3, b00, b01);
        MMA16816(acc[1], a0, a1, a2, a3, b10, b11);
    }

    bool partial = (gridDim.z > 1);
    float* Cp = partial ? (Cf + (size_t)blockIdx.z * ((size_t)gridDim.y * 32) * Nn)
                        : Cf;
#pragma unroll
    for (int nf = 0; nf < 2; nf++) {
        int row = m0 + wm * 16 + (lane >> 2);
        int col = n0 + wn * 16 + nf * 8 + (lane & 3) * 2;
#pragma unroll
        for (int half = 0; half < 2; half++) {
            int r = row + half * 8;
            float v0 = acc[nf][half * 2 + 0];
            float v1 = acc[nf][half * 2 + 1];
            if (partial) {
                *(float2*)&Cp[(size_t)r * Nn + col] = make_float2(v0, v1);
                continue;
            }
            v0 += bias[col];
            v1 += bias[col + 1];
            if (mode == 3) {
                const float* pp = &pos[(size_t)(r & 255) * Nn + col];
                v0 += pp[0]; v1 += pp[1];
            }
            if (mode == 1) {
                v0 = 0.5f * v0 * (1.0f + erff(v0 * 0.7071067811865475f));
                v1 = 0.5f * v1 * (1.0f + erff(v1 * 0.7071067811865475f));
                *(uint32_t*)&Cb[(size_t)r * Nn + col] = pack_bf2(v0, v1);
            } else {
                float* cp = &Cf[(size_t)r * Nn + col];
                if (mode == 2) { v0 += cp[0]; v1 += cp[1]; }
                *(float2*)cp = make_float2(v0, v1);
            }
        }
    }
}

__global__ void ln_kernel(const float* __restrict__ in,
                          const float* __restrict__ gam,
                          const float* __restrict__ bet,
                          __nv_bfloat16* __restrict__ out) {
    int gid = blockIdx.x * blockDim.x + threadIdx.x;
    int row = gid >> 5, lane = gid & 31;
    const float4* r4 = (const float4*)(in + (size_t)row * DD);
    float4 a = r4[lane * 2], b = r4[lane * 2 + 1];
    float s = (a.x + a.y) + (a.z + a.w) + (b.x + b.y) + (b.z + b.w);
#pragma unroll
    for (int o = 16; o; o >>= 1) s += __shfl_xor_sync(0xffffffffu, s, o);
    float mean = s * (1.0f / DD);
    float d0 = a.x - mean, d1 = a.y - mean, d2 = a.z - mean, d3 = a.w - mean;
    float d4 = b.x - mean, d5 = b.y - mean, d6 = b.z - mean, d7 = b.w - mean;
    float sq = d0*d0 + d1*d1 + d2*d2 + d3*d3 + d4*d4 + d5*d5 + d6*d6 + d7*d7;
#pragma unroll
    for (int o = 16; o; o >>= 1) sq += __shfl_xor_sync(0xffffffffu, sq, o);
    float rs = rsqrtf(sq * (1.0f / DD) + 1e-5f);
    float4 g0 = ((const float4*)gam)[lane * 2], g1 = ((const float4*)gam)[lane * 2 + 1];
    float4 b0 = ((const float4*)bet)[lane * 2], b1 = ((const float4*)bet)[lane * 2 + 1];
    uint4 u;
    u.x = pack_bf2(d0*rs*g0.x + b0.x, d1*rs*g0.y + b0.y);
    u.y = pack_bf2(d2*rs*g0.z + b0.z, d3*rs*g0.w + b0.w);
    u.z = pack_bf2(d4*rs*g1.x + b1.x, d5*rs*g1.y + b1.y);
    u.w = pack_bf2(d6*rs*g1.z + b1.z, d7*rs*g1.w + b1.w);
    *(uint4*)(out + (size_t)row * DD + lane * 8) = u;
}

__global__ void combine_ln_kernel(const float* __restrict__ bias,
                                  const float* __restrict__ gam,
                                  const float* __restrict__ bet,
                                  int doLN) {
    int gid = blockIdx.x * blockDim.x + threadIdx.x;
    int row = gid >> 5, lane = gid & 31;
    size_t base = (size_t)row * DD + lane * 8;
    float v[8];
    {
        float4 z0 = *(const float4*)&g_z[base];
        float4 z1 = *(const float4*)&g_z[base + 4];
        float4 b0 = *(const float4*)&bias[lane * 8];
        float4 b1 = *(const float4*)&bias[lane * 8 + 4];
        v[0] = z0.x + b0.x; v[1] = z0.y + b0.y;
        v[2] = z0.z + b0.z; v[3] = z0.w + b0.w;
        v[4] = z1.x + b1.x; v[5] = z1.y + b1.y;
        v[6] = z1.z + b1.z; v[7] = z1.w + b1.w;
    }
#pragma unroll
    for (int p = 0; p < 4; p++) {
        float4 p0 = *(const float4*)&g_gpart[(size_t)p * TOT + base];
        float4 p1 = *(const float4*)&g_gpart[(size_t)p * TOT + base + 4];
        v[0] += p0.x; v[1] += p0.y; v[2] += p0.z; v[3] += p0.w;
        v[4] += p1.x; v[5] += p1.y; v[6] += p1.z; v[7] += p1.w;
    }
    *(float4*)&g_z[base]     = make_float4(v[0], v[1], v[2], v[3]);
    *(float4*)&g_z[base + 4] = make_float4(v[4], v[5], v[6], v[7]);
    if (doLN) {
        float s = (v[0]+v[1])+(v[2]+v[3])+(v[4]+v[5])+(v[6]+v[7]);
#pragma unroll
        for (int o = 16; o; o >>= 1) s += __shfl_xor_sync(0xffffffffu, s, o);
        float mean = s * (1.0f / DD);
        float d[8], sq = 0.f;
#pragma unroll
        for (int j = 0; j < 8; j++) { d[j] = v[j] - mean; sq += d[j]*d[j]; }
#pragma unroll
        for (int o = 16; o; o >>= 1) sq += __shfl_xor_sync(0xffffffffu, sq, o);
        float rs = rsqrtf(sq * (1.0f / DD) + 1e-5f);
        float4 g0 = ((const float4*)gam)[lane*2], g1 = ((const float4*)gam)[lane*2+1];
        float4 e0 = ((const float4*)bet)[lane*2], e1 = ((const float4*)bet)[lane*2+1];
        uint4 u;
        u.x = pack_bf2(d[0]*rs*g0.x + e0.x, d[1]*rs*g0.y + e0.y);
        u.y = pack_bf2(d[2]*rs*g0.z + e0.z, d[3]*rs*g0.w + e0.w);
        u.z = pack_bf2(d[4]*rs*g1.x + e1.x, d[5]*rs*g1.y + e1.y);
        u.w = pack_bf2(d[6]*rs*g1.z + e1.z, d[7]*rs*g1.w + e1.w);
        *(uint4*)(g_yb + base) = u;
    } else {
        uint4 u;
        u.x = pack_bf2(v[0], v[1]); u.y = pack_bf2(v[2], v[3]);
        u.z = pack_bf2(v[4], v[5]); u.w = pack_bf2(v[6], v[7]);
        *(uint4*)(g_zb + base) = u;
    }
}

__global__ void attn_kernel() {
    __shared__ float ks [128 * HD];
    __shared__ float vsm[128 * HD];
    int bi  = blockIdx.x;
    int kvh = bi & 1, qh = (bi >> 1) & 1, h = (bi >> 2) & 7, b = bi >> 5;
    for (int i = threadIdx.x; i < 128 * HD; i += 128) {
        int m = i >> 5, c = i & 31;
        const float* base = g_qkv + ((size_t)(b * NTOK + kvh * 128 + m)) * (3 * DD) + h * HD + c;
        ks[i]  = base[DD];
        vsm[i] = base[2 * DD];
    }
    __syncthreads();
    int q = qh * 128 + threadIdx.x;
    const float* qr = g_qkv + (size_t)(b * NTOK + q) * (3 * DD) + h * HD;
    float qv[HD];
#pragma unroll
    for (int c = 0; c < HD; c++) qv[c] = qr[c] * 0.17677669529663687f;
    float mmax = -1e30f, l = 0.f, acc[HD];
#pragma unroll
    for (int c = 0; c < HD; c++) acc[c] = 0.f;
    for (int m = 0; m < 128; m++) {
        const float4* kp = (const float4*)&ks[m * HD];
        float s0 = 0.f, s1 = 0.f, s2 = 0.f, s3 = 0.f;
#pragma unroll
        for (int j = 0; j < 8; j++) {
            float4 k4 = kp[j];
            s0 += qv[j*4+0] * k4.x; s1 += qv[j*4+1] * k4.y;
            s2 += qv[j*4+2] * k4.z; s3 += qv[j*4+3] * k4.w;
        }
        float sc = (s0 + s1) + (s2 + s3);
        float nm   = fmaxf(mmax, sc);
        float corr = __expf(mmax - nm);
        float p    = __expf(sc - nm);
        l = l * corr + p;
        const float4* vp = (const float4*)&vsm[m * HD];
#pragma unroll
        for (int j = 0; j < 8; j++) {
            float4 v4 = vp[j];
            acc[j*4+0] = acc[j*4+0] * corr + p * v4.x;
            acc[j*4+1] = acc[j*4+1] * corr + p * v4.y;
            acc[j*4+2] = acc[j*4+2] * corr + p * v4.z;
            acc[j*4+3] = acc[j*4+3] * corr + p * v4.w;
        }
        mmax = nm;
    }
    int pidx = ((b * NHH + h) * NTOK + q) * 2 + kvh;
    g_pm[pidx] = mmax;
    g_pl[pidx] = l;
    float4* pa = (float4*)&g_pacc[(size_t)pidx * HD];
#pragma unroll
    for (int j = 0; j < 8; j++)
        pa[j] = make_float4(acc[j*4+0], acc[j*4+1], acc[j*4+2], acc[j*4+3]);
}

__global__ void conv_up_kernel(const float* __restrict__ cw,
                               const float* __restrict__ cb,
                               float* __restrict__ out) {
    int idx = blockIdx.x * blockDim.x + threadIdx.x;
    if (idx >= IMG) return;
    int x = idx & 255, y = (idx >> 8) & 255, b = idx >> 16;
    float s = 0.f;
#pragma unroll
    for (int ky = 0; ky < 3; ky++) {
        int yy = y + ky - 1;
        if (yy < 0 || yy >= NY) continue;
#pragma unroll
        for (int kx = 0; kx < 3; kx++) {
            int xx = x + kx - 1;
            if (xx < 0 || xx >= NX) continue;
            float v = g_pix[(size_t)((b << 8) + (yy >> 4) * 16 + (xx >> 4)) * DD
                            + (yy & 15) * 16 + (xx & 15)];
            s += v * cw[ky * 3 + kx];
        }
    }
    out[idx] = s + cb[0] + g_bp[idx];
}

extern "C" void kernel_launch(void* const* d_in, const int* in_sizes, int n_in,
                              void* d_out, int out_size) {
    const float* sino    = (const float*)d_in[0];
    const float* lut     = (const float*)d_in[1];
    const float* patch_w = (const float*)d_in[2];
    const float* patch_b = (const float*)d_in[3];
    const float* pos     = (const float*)d_in[4];
    const float* ln1_g   = (const float*)d_in[5];
    const float* ln1_b   = (const float*)d_in[6];
    const float* wqkv    = (const float*)d_in[7];
    const float* bqkv    = (const float*)d_in[8];
    const float* wo      = (const float*)d_in[9];
    const float* bo      = (const float*)d_in[10];
    const float* ln2_g   = (const float*)d_in[11];
    const float* ln2_b   = (const float*)d_in[12];
    const float* w1      = (const float*)d_in[13];
    const float* b1      = (const float*)d_in[14];
    const float* w2      = (const float*)d_in[15];
    const float* b2      = (const float*)d_in[16];
    const float* proj_w  = (const float*)d_in[17];
    const float* proj_b  = (const float*)d_in[18];
    const float* conv_w  = (const float*)d_in[19];
    const float* conv_b  = (const float*)d_in[20];

    float* out = (float*)d_out;
    float* out_bp = (out_size >= 2 * IMG) ? (out + IMG) : nullptr;

    cudaFuncSetAttribute(bp_stage4_kernel, cudaFuncAttributeMaxDynamicSharedMemorySize, 131072);
    cudaFuncSetAttribute(gemm_mma, cudaFuncAttributeMaxDynamicSharedMemorySize, SMEM_GM);

    __nv_bfloat16 *wb, *yb, *h1b, *zb;
    float *z, *qkv, *pix, *gp;
    cudaGetSymbolAddress((void**)&wb,   g_wb);
    cudaGetSymbolAddress((void**)&yb,   g_yb);
    cudaGetSymbolAddress((void**)&h1b,  g_h1b);
    cudaGetSymbolAddress((void**)&zb,   g_zb);
    cudaGetSymbolAddress((void**)&z,    g_z);
    cudaGetSymbolAddress((void**)&qkv,  g_qkv);
    cudaGetSymbolAddress((void**)&pix,  g_pix);
    cudaGetSymbolAddress((void**)&gp,   g_gpart);

    wconv_kernel<<<WTOT / 256, 256>>>(patch_w, wqkv, wo, w1, w2, proj_w);

    bp_stage4_kernel<<<dim3(8, 32), 256, 131072>>>(sino, lut);
    bp_reduce_kernel<<<IMG / 256, 256>>>(out_bp);

    gemm_mma<<<dim3(4, 32), 256, SMEM_GM>>>(nullptr, wb + OFF_PATCH, patch_b,
                                            z, nullptr, pos, DD, DD, 3, 1);
    ln_kernel<<<MTOK / 8, 256>>>(z, ln1_g, ln1_b, yb);

    for (int l = 0; l < LL; l++) {
        gemm_mma<<<dim3(12, 32), 256, SMEM_GM>>>(
            yb, wb + OFF_QKV + (size_t)l * 3 * DD * DD, bqkv + (size_t)l * 3 * DD,
            qkv, nullptr, nullptr, DD, 3 * DD, 0, 0);
        attn_kernel<<<BB * NHH * 4, 128>>>();
        gemm_mma<<<dim3(4, 32), 256, SMEM_GM>>>(
            nullptr, wb + OFF_WO + (size_t)l * DD * DD, bo + (size_t)l * DD,
            z, nullptr, nullptr, DD, DD, 2, 2);
        ln_kernel<<<MTOK / 8, 256>>>(z, ln2_g + (size_t)l * DD,
                                     ln2_b + (size_t)l * DD, yb);
        gemm_mma<<<dim3(16, 32), 256, SMEM_GM>>>(
            yb, wb + OFF_W1 + (size_t)l * 4 * DD * DD, b1 + (size_t)l * 4 * DD,
            nullptr, h1b, nullptr, DD, 4 * DD, 1, 0);
        gemm_mma<<<dim3(4, 32, 4), 256, SMEM_GM>>>(
            h1b, wb + OFF_W2 + (size_t)l * DD * 4 * DD, nullptr,
            gp, nullptr, nullptr, 4 * DD, DD, 0, 0);
        if (l < LL - 1)
            combine_ln_kernel<<<MTOK * 32 / 256, 256>>>(
                b2 + (size_t)l * DD, ln1_g + (size_t)(l + 1) * DD,
                ln1_b + (size_t)(l + 1) * DD, 1);
        else
            combine_ln_kernel<<<MTOK * 32 / 256, 256>>>(
                b2 + (size_t)l * DD, nullptr, nullptr, 0);
    }

    gemm_mma<<<dim3(4, 32), 256, SMEM_GM>>>(zb, wb + OFF_PROJ, proj_b, pix,
                                            nullptr, nullptr, DD, DD, 0, 0);
    conv_up_kernel<<<IMG / 256, 256>>>(conv_w, conv_b, out);
}